// round 16
// baseline (speedup 1.0000x reference)
#include <cuda_runtime.h>
#include <cstdint>

#define BB 128
#define TT 4096
#define NP (BB*TT)
#define NCHUNK 128               // 32 planes per chunk
#define CLIPV 100000.0f
#define K10  (-14.4269504088896340f)   // -10*log2(e)
#define KS1  (-1.4426950408889634f)    // -1*log2(e)  (sigmoid)
#define LFR  (0.14426950408889634f)    // 0.1*log2(e)

// ---------------- scratch (device-global, no allocation) ----------------
__device__ float4 g_pA[(TT+16)*BB];   // psnow, prain, g(melt gate), m2(melt cap)
__device__ float4 g_pB[(TT+16)*BB];   // C1t=-5*smax, C3=pet+qmax-smax, Bc=pet/smax, fr2
__device__ float2 g_pC[(TT+16)*BB];   // C2=log2(qmax)-fr2*smax, C4=qmax-smax
__device__ float  g_s1s[TT*BB];       // s1 trajectory
__device__ int    g_flag[NCHUNK];     // per-chunk completion counters (0..64)

typedef unsigned long long ull;

__device__ __forceinline__ float ex2f(float x){ float y; asm("ex2.approx.f32 %0, %1;" : "=f"(y) : "f"(x)); return y; }
__device__ __forceinline__ float rcpf(float x){ float y; asm("rcp.approx.f32 %0, %1;" : "=f"(y) : "f"(x)); return y; }
__device__ __forceinline__ float lg2f(float x){ float y; asm("lg2.approx.f32 %0, %1;" : "=f"(y) : "f"(x)); return y; }
__device__ __forceinline__ float th_hw(float x){ float y; asm("tanh.approx.f32 %0, %1;" : "=f"(y) : "f"(x)); return y; }
__device__ __forceinline__ float hv10(float x){ return rcpf(1.f + ex2f(K10 * x)); }
__device__ __forceinline__ float sigm(float x){ return rcpf(1.f + ex2f(KS1 * x)); }
__device__ __forceinline__ int ld_acq(const int* p){ int v; asm volatile("ld.acquire.gpu.global.b32 %0, [%1];" : "=r"(v) : "l"(p)); return v; }

__device__ __forceinline__ ull pk(float lo, float hi){ ull r; asm("mov.b64 %0, {%1, %2};" : "=l"(r) : "f"(lo), "f"(hi)); return r; }
__device__ __forceinline__ void upk(ull v, float& lo, float& hi){ asm("mov.b64 {%0, %1}, %2;" : "=f"(lo), "=f"(hi) : "l"(v)); }
__device__ __forceinline__ ull ffma2(ull a, ull b, ull c){ ull d; asm("fma.rn.f32x2 %0, %1, %2, %3;" : "=l"(d) : "l"(a), "l"(b), "l"(c)); return d; }
__device__ __forceinline__ ull fadd2(ull a, ull b){ ull d; asm("add.rn.f32x2 %0, %1, %2;" : "=l"(d) : "l"(a), "l"(b)); return d; }
__device__ __forceinline__ ull tanh2hw(ull v){ float lo, hi; upk(v, lo, hi); return pk(th_hw(lo), th_hw(hi)); }
__device__ __forceinline__ ull shfl16(ull v){
    unsigned lo = (unsigned)v, hi = (unsigned)(v >> 32);
    lo = __shfl_down_sync(0xffffffffu, lo, 16);
    hi = __shfl_down_sync(0xffffffffu, hi, 16);
    return ((ull)hi << 32) | lo;
}

// ---------------- SMEM layout (floats), 64-position tile, 128-row H window ----------------
#define ATT_OFF 0                        // attrs[15][64]
#define PT_OFF  (ATT_OFF + 15*64)        // pt[3][64]
#define W1D_OFF (PT_OFF + 3*64)          // w1 dup [15][512]  (reused as g later)
#define B1_OFF  (W1D_OFF + 15*512)       // 256
#define B2_OFF  (B1_OFF + 256)           // 64
#define W3_OFF  (B2_OFF + 64)            // w3t[6][64]
#define B3_OFF  (W3_OFF + 6*64)          // 8
#define H_OFF   (B3_OFF + 8)             // h window [128][64]
#define G_OFF   W1D_OFF                  // g[64][68] pos-major, padded (overlays w1d)
#define GPITCH  68
#define SMEM_FLOATS (H_OFF + 128*64)
#define SMEM_BYTES (SMEM_FLOATS * 4)     // 70944 B -> 3 CTAs/SM

__device__ __forceinline__ void emit_consts(int idx, float pet, float tmean, float prcp, const float p[6]){
    float tmin = p[0], tmax = p[1], ddf = p[2], f = p[3], sm0 = p[4], qm0 = p[5];
    float smax = fmaf(sm0, 1400.f, 100.f);
    float qmax = fmaf(qm0, 40.f, 10.f);
    float tmn   = tmin * (-3.f);
    float psnow = hv10(tmn - tmean) * prcp;
    float prain = prcp - psnow;
    float tmx3  = tmax * 3.f;
    float g     = hv10(tmean - tmx3);
    float m2    = (ddf * 5.f) * (tmean - tmx3);
    float fr2   = f * LFR;
    float C1t   = -5.f * smax;
    float C3    = pet + qmax - smax;
    float Bc    = pet * rcpf(smax);
    float C2    = lg2f(qmax) - fr2 * smax;
    float C4    = qmax - smax;
    g_pA[idx] = make_float4(psnow, prain, g, m2);
    g_pB[idx] = make_float4(C1t, C3, Bc, fr2);
    g_pC[idx] = make_float2(C2, C4);
}

// ============ kernel A: zero the chunk flags ============
__global__ void zero_flags(){
    if (threadIdx.x < NCHUNK) g_flag[threadIdx.x] = 0;
}

// ============ scan (device function, run by CTAs 0..3) ============
__device__ void scan_body(int bid, int lane)
{
    const int b = bid * 32 + lane;
    const float4* pA = g_pA + b;
    const float4* pB = g_pB + b;
    const float2* pC = g_pC + b;

    // wait for chunk 0, then fill the 8-deep ring
    while (ld_acq(&g_flag[0]) < 64) __nanosleep(200);
    float4 bA[8], bC[8]; float bL[8];
    #pragma unroll
    for (int k = 0; k < 8; k++){
        bA[k] = pA[k*BB]; bC[k] = pB[k*BB]; bL[k] = pC[k*BB].x;
    }

    float s0 = 0.f, s1 = 0.f;
    #pragma unroll 1
    for (int c = 0; c < NCHUNK; c++){
        // one poll per 32 steps: chunk c+1 covers the <=8-plane prefetch lookahead
        const int wc = (c + 1 < NCHUNK) ? c + 1 : NCHUNK - 1;
        while (ld_acq(&g_flag[wc]) < 64) __nanosleep(200);

        #pragma unroll 1
        for (int t = c*32; t < c*32 + 32; t += 8){
            #pragma unroll
            for (int u = 0; u < 8; u++){
                float4 a = bA[u]; float4 cc = bC[u]; float lq = bL[u];
                int tn = t + u + 8; if (tn > TT-1) tn = TT-1;
                bA[u] = pA[tn*BB]; bC[u] = pB[tn*BB]; bL[u] = pC[tn*BB].x;

                // ---- snow bucket:  s0 += clip(psnow - melt) ----
                float s0pa = s0 + a.x;
                float s0lo = s0 - CLIPV, s0hi = s0 + CLIPV;
                float m0   = a.z * fminf(s0, a.w);
                float hs0  = fmaf(0.5f, th_hw(5.f * s0), 0.5f);
                float melt = hs0 * m0;

                // ---- soil bucket:  s1 += clip(prain + melt - loss) ----
                float s1lo = s1 - CLIPV, s1hi = s1 + CLIPV;
                float ays  = (a.y + s1);
                float tA    = th_hw(fmaf(5.f, s1, cc.x));
                float above = fmaf(0.5f, tA, 0.5f);
                float h1    = fmaf(0.5f, th_hw(5.f * s1), 0.5f);
                float E     = ex2f(fmaf(cc.w, s1, lq));
                float v     = fmaf(cc.z, s1, E);
                float g     = (cc.y + s1) - v;
                float w     = fmaf(above, g, v);
                float aym   = ays + melt;
                s1 = fmaxf(fminf(fmaf(-h1, w, aym), s1hi), s1lo);
                s0 = fmaxf(fminf(s0pa - melt, s0hi), s0lo);

                g_s1s[(t + u) * BB + b] = s1;
            }
        }
    }
}

// ---- stage A for one 128-row hidden window ----
__device__ __forceinline__ void stageA_win(float* sm, int half, int bg, int ig)
{
    #pragma unroll 1
    for (int pass = 0; pass < 2; pass++){
        const int i0   = half*128 + pass*64 + ig*4;   // global hidden index
        const int hrow = pass*64 + ig*4;              // row in H window
        ull accL[4], accH[4];
        #pragma unroll
        for (int ii = 0; ii < 4; ii++){
            float bb = sm[B1_OFF + i0 + ii];
            accL[ii] = pk(bb, bb); accH[ii] = accL[ii];
        }
        #pragma unroll
        for (int k = 0; k < 15; k++){
            ull aL = *(const ull*)(sm + ATT_OFF + k*64 + bg*2);
            ull aH = *(const ull*)(sm + ATT_OFF + k*64 + 32 + bg*2);
            ulonglong2 w01 = *(const ulonglong2*)(sm + W1D_OFF + k*512 + i0*2);
            ulonglong2 w23 = *(const ulonglong2*)(sm + W1D_OFF + k*512 + i0*2 + 4);
            accL[0]=ffma2(aL,w01.x,accL[0]); accL[1]=ffma2(aL,w01.y,accL[1]);
            accL[2]=ffma2(aL,w23.x,accL[2]); accL[3]=ffma2(aL,w23.y,accL[3]);
            accH[0]=ffma2(aH,w01.x,accH[0]); accH[1]=ffma2(aH,w01.y,accH[1]);
            accH[2]=ffma2(aH,w23.x,accH[2]); accH[3]=ffma2(aH,w23.y,accH[3]);
        }
        #pragma unroll
        for (int ii = 0; ii < 4; ii++){
            *(ull*)(sm + H_OFF + (hrow+ii)*64 + bg*2)      = tanh2hw(accL[ii]);
            *(ull*)(sm + H_OFF + (hrow+ii)*64 + 32 + bg*2) = tanh2hw(accH[ii]);
        }
    }
}

// ---- stage B accumulation over one 128-row window (64 rows per kg half) ----
__device__ __forceinline__ void stageB_win(
    ull acc[4][4], const float* sm, const float* __restrict__ w2,
    int winbase, int kg, int pg, int j0)
{
    const int r0 = winbase + kg*64;
    const char* rw = (const char*)(w2 + r0*64 + j0);   // row stride 256 B
    ulonglong2 wb[2][2];
    wb[0][0] = __ldg((const ulonglong2*)rw);         wb[0][1] = __ldg((const ulonglong2*)rw + 1);
    wb[1][0] = __ldg((const ulonglong2*)(rw+256));   wb[1][1] = __ldg((const ulonglong2*)(rw+256) + 1);

    #pragma unroll 2
    for (int ii = 0; ii < 64; ii++){
        const int slot = ii & 1;
        ull q0 = wb[slot][0].x, q1 = wb[slot][0].y;
        ull q2 = wb[slot][1].x, q3 = wb[slot][1].y;
        int nr = r0 + ii + 2; if (nr > 255) nr = 255;   // clamp (last window tail)
        const ulonglong2* rp = (const ulonglong2*)(w2 + nr*64 + j0);
        wb[slot][0] = __ldg(rp); wb[slot][1] = __ldg(rp + 1);

        float4 hq = *(const float4*)(sm + H_OFF + (kg*64+ii)*64 + pg*4);
        ull h0 = pk(hq.x,hq.x), h1 = pk(hq.y,hq.y), h2 = pk(hq.z,hq.z), h3 = pk(hq.w,hq.w);
        acc[0][0]=ffma2(h0,q0,acc[0][0]); acc[0][1]=ffma2(h0,q1,acc[0][1]); acc[0][2]=ffma2(h0,q2,acc[0][2]); acc[0][3]=ffma2(h0,q3,acc[0][3]);
        acc[1][0]=ffma2(h1,q0,acc[1][0]); acc[1][1]=ffma2(h1,q1,acc[1][1]); acc[1][2]=ffma2(h1,q2,acc[1][2]); acc[1][3]=ffma2(h1,q3,acc[1][3]);
        acc[2][0]=ffma2(h2,q0,acc[2][0]); acc[2][1]=ffma2(h2,q1,acc[2][1]); acc[2][2]=ffma2(h2,q2,acc[2][2]); acc[2][3]=ffma2(h2,q3,acc[2][3]);
        acc[3][0]=ffma2(h3,q0,acc[3][0]); acc[3][1]=ffma2(h3,q1,acc[3][1]); acc[3][2]=ffma2(h3,q2,acc[3][2]); acc[3][3]=ffma2(h3,q3,acc[3][3]);
    }
}

// ============ fused kernel: mlp producer CTAs + scan consumer CTAs ============
__global__ __launch_bounds__(256, 3)
void fused_kernel(const float* __restrict__ in,
                  const float* __restrict__ w1, const float* __restrict__ b1,
                  const float* __restrict__ w2, const float* __restrict__ b2,
                  const float* __restrict__ w3, const float* __restrict__ b3)
{
    const int bid = blockIdx.x;
    const int tid = threadIdx.x;

    if (bid < 4){
        if (tid < 32) scan_body(bid, tid);
        return;
    }

    extern __shared__ float sm[];
    const int t   = (bid - 4) >> 1;
    const int hb  = (bid - 4) & 1;         // which 64-position half

    // ---- stage inputs ----
    {
        int r = tid >> 2, part = tid & 3;          // r: local row 0..63
        const float* base = in + ((size_t)(hb*64 + r) * TT + t) * 20;
        float4 q = *(const float4*)(base + part*4);
        if (part == 0){
            sm[PT_OFF + 0*64 + r] = q.x;           // pet
            sm[PT_OFF + 1*64 + r] = q.y;           // tmean
            sm[PT_OFF + 2*64 + r] = q.z;           // prcp
            float4 q4 = *(const float4*)(base + 16);
            sm[ATT_OFF + 11*64 + r] = q4.x; sm[ATT_OFF + 12*64 + r] = q4.y;
            sm[ATT_OFF + 13*64 + r] = q4.z; sm[ATT_OFF + 14*64 + r] = q4.w;
        } else if (part == 1){
            sm[ATT_OFF + 0*64 + r] = q.y; sm[ATT_OFF + 1*64 + r] = q.z; sm[ATT_OFF + 2*64 + r] = q.w;
        } else if (part == 2){
            sm[ATT_OFF + 3*64 + r] = q.x; sm[ATT_OFF + 4*64 + r] = q.y;
            sm[ATT_OFF + 5*64 + r] = q.z; sm[ATT_OFF + 6*64 + r] = q.w;
        } else {
            sm[ATT_OFF + 7*64 + r] = q.x; sm[ATT_OFF + 8*64 + r] = q.y;
            sm[ATT_OFF + 9*64 + r] = q.z; sm[ATT_OFF +10*64 + r] = q.w;
        }
    }
    // ---- stage duplicated w1 (dup at staging time) + small weights ----
    for (int idx = tid; idx < 15*256; idx += 256){
        int k = idx >> 8, i = idx & 255;
        float w = w1[idx];
        sm[W1D_OFF + k*512 + 2*i]     = w;
        sm[W1D_OFF + k*512 + 2*i + 1] = w;
    }
    sm[B1_OFF + tid] = b1[tid];
    if (tid < 64) sm[B2_OFF + tid] = b2[tid];
    for (int i = tid; i < 384; i += 256){ int m = i >> 6, j = i & 63; sm[W3_OFF + i] = w3[j*6 + m]; }
    if (tid < 8) sm[B3_OFF + tid] = (tid < 6) ? b3[tid] : 0.f;
    __syncthreads();

    const int bg   = tid & 15;        // stage A: pos pairs
    const int ig   = tid >> 4;        // stage A: hidden groups of 4
    const int lane = tid & 31;
    const int wrp  = tid >> 5;        // stage B: warp = output group; j0 = wrp*8
    const int j0   = wrp * 8;
    const int pg   = lane & 15;       // stage B: 4 positions p0 = pg*4
    const int kg   = lane >> 4;       // stage B: 64-row half of the window

    // ---- persistent layer-2 accumulators ----
    ull acc[4][4];
    #pragma unroll
    for (int m = 0; m < 4; m++){
        ull bv = (kg == 0) ? *(const ull*)(sm + B2_OFF + j0 + 2*m) : 0ULL;
        acc[0][m] = bv; acc[1][m] = bv; acc[2][m] = bv; acc[3][m] = bv;
    }

    // ---- window 0: hidden 0..127 ----
    stageA_win(sm, 0, bg, ig);
    __syncthreads();
    stageB_win(acc, sm, w2, 0, kg, pg, j0);
    __syncthreads();                    // stage B done reading H window

    // ---- window 1: hidden 128..255 ----
    stageA_win(sm, 1, bg, ig);
    __syncthreads();
    stageB_win(acc, sm, w2, 128, kg, pg, j0);

    // ---- split-K reduction (lanes 16..31 -> 0..15) ----
    #pragma unroll
    for (int p = 0; p < 4; p++)
        #pragma unroll
        for (int m = 0; m < 4; m++)
            acc[p][m] = fadd2(acc[p][m], shfl16(acc[p][m]));

    __syncthreads();   // all h/w1d reads done; w1d region becomes g

    if (kg == 0){
        #pragma unroll
        for (int p = 0; p < 4; p++){
            const int row = pg*4 + p;
            ulonglong2 v01, v23;
            v01.x = tanh2hw(acc[p][0]); v01.y = tanh2hw(acc[p][1]);
            v23.x = tanh2hw(acc[p][2]); v23.y = tanh2hw(acc[p][3]);
            *(ulonglong2*)(sm + G_OFF + row*GPITCH + j0)     = v01;
            *(ulonglong2*)(sm + G_OFF + row*GPITCH + j0 + 4) = v23;
        }
    }
    __syncthreads();

    // ---- stage C: layer 3 (64 -> 6) + sigmoid + emit ----
    if (tid < 64){
        const int b = tid;
        float s0c = sm[B3_OFF+0], s1c = sm[B3_OFF+1], s2c = sm[B3_OFF+2];
        float s3c = sm[B3_OFF+3], s4c = sm[B3_OFF+4], s5c = sm[B3_OFF+5];
        #pragma unroll
        for (int j = 0; j < 64; j += 4){
            float4 gq = *(const float4*)(sm + G_OFF + b*GPITCH + j);
            #pragma unroll
            for (int u = 0; u < 4; u++){
                float gv = (&gq.x)[u];
                s0c = fmaf(gv, sm[W3_OFF + 0*64 + j + u], s0c);
                s1c = fmaf(gv, sm[W3_OFF + 1*64 + j + u], s1c);
                s2c = fmaf(gv, sm[W3_OFF + 2*64 + j + u], s2c);
                s3c = fmaf(gv, sm[W3_OFF + 3*64 + j + u], s3c);
                s4c = fmaf(gv, sm[W3_OFF + 4*64 + j + u], s4c);
                s5c = fmaf(gv, sm[W3_OFF + 5*64 + j + u], s5c);
            }
        }
        float pr[6] = { sigm(s0c), sigm(s1c), sigm(s2c), sigm(s3c), sigm(s4c), sigm(s5c) };
        emit_consts(t*128 + hb*64 + b, sm[PT_OFF + b], sm[PT_OFF + 64 + b], sm[PT_OFF + 128 + b], pr);
    }

    // ---- publish chunk progress (release) ----
    __threadfence();
    __syncthreads();
    if (tid == 0) atomicAdd(&g_flag[t >> 5], 1);
}

// ============ kernel C: q = qsub+qsurf from stored s1 ============
__global__ __launch_bounds__(256)
void qout_kernel(float* __restrict__ out)
{
    int idx = blockIdx.x * 256 + threadIdx.x;
    if (idx >= NP) return;
    float  s1 = g_s1s[idx];
    float4 c  = g_pB[idx];   // C1t, C3, Bc, fr2
    float2 e  = g_pC[idx];   // C2, C4
    float tA    = th_hw(fmaf(5.f, s1, c.x));
    float above = fmaf( 0.5f, tA, 0.5f);
    float below = fmaf(-0.5f, tA, 0.5f);
    float h1    = fmaf(0.5f, th_hw(5.f * s1), 0.5f);
    float E     = ex2f(fmaf(c.w, s1, e.x));
    float q     = h1 * (above * (e.y + s1) + below * E);
    int t = idx >> 7, b = idx & 127;
    out[(size_t)b * TT + t] = q;
}

// ---------------- launch ----------------
extern "C" void kernel_launch(void* const* d_in, const int* in_sizes, int n_in,
                              void* d_out, int out_size)
{
    const float* in = (const float*)d_in[0];
    const float* w1 = (const float*)d_in[1];
    const float* b1 = (const float*)d_in[2];
    const float* w2 = (const float*)d_in[3];
    const float* b2 = (const float*)d_in[4];
    const float* w3 = (const float*)d_in[5];
    const float* b3 = (const float*)d_in[6];
    float* out = (float*)d_out;

    zero_flags<<<1, 128>>>();
    cudaFuncSetAttribute(fused_kernel, cudaFuncAttributeMaxDynamicSharedMemorySize, SMEM_BYTES);
    fused_kernel<<<TT*2 + 4, 256, SMEM_BYTES>>>(in, w1, b1, w2, b2, w3, b3);
    qout_kernel<<<(NP + 255)/256, 256>>>(out);
}

// round 17
// speedup vs baseline: 2.4685x; 2.4685x over previous
#include <cuda_runtime.h>
#include <cstdint>

#define BB 128
#define TT 4096
#define NP (BB*TT)
#define NCHUNK 128               // 32 planes per chunk
#define CLIPV 100000.0f
#define K10  (-14.4269504088896340f)   // -10*log2(e)
#define KS1  (-1.4426950408889634f)    // -1*log2(e)  (sigmoid)
#define LFR  (0.14426950408889634f)    // 0.1*log2(e)

// ---------------- scratch (device-global, no allocation) ----------------
__device__ float4 g_pA[(TT+16)*BB];   // psnow, prain, g(melt gate), m2(melt cap)
__device__ float4 g_pB[(TT+16)*BB];   // C1t=-5*smax, C3=pet+qmax-smax, Bc=pet/smax, fr2
__device__ float2 g_pC[(TT+16)*BB];   // C2=log2(qmax)-fr2*smax, C4=qmax-smax
__device__ float  g_s1s[TT*BB];       // s1 trajectory
__device__ int    g_flag[NCHUNK];     // per-chunk completion counters (0..64); re-zeroed by qout tail

typedef unsigned long long ull;

__device__ __forceinline__ float ex2f(float x){ float y; asm("ex2.approx.f32 %0, %1;" : "=f"(y) : "f"(x)); return y; }
__device__ __forceinline__ float rcpf(float x){ float y; asm("rcp.approx.f32 %0, %1;" : "=f"(y) : "f"(x)); return y; }
__device__ __forceinline__ float lg2f(float x){ float y; asm("lg2.approx.f32 %0, %1;" : "=f"(y) : "f"(x)); return y; }
__device__ __forceinline__ float th_hw(float x){ float y; asm("tanh.approx.f32 %0, %1;" : "=f"(y) : "f"(x)); return y; }
__device__ __forceinline__ float hv10(float x){ return rcpf(1.f + ex2f(K10 * x)); }
__device__ __forceinline__ float sigm(float x){ return rcpf(1.f + ex2f(KS1 * x)); }
__device__ __forceinline__ int ld_acq(const int* p){ int v; asm volatile("ld.acquire.gpu.global.b32 %0, [%1];" : "=r"(v) : "l"(p)); return v; }

__device__ __forceinline__ ull pk(float lo, float hi){ ull r; asm("mov.b64 %0, {%1, %2};" : "=l"(r) : "f"(lo), "f"(hi)); return r; }
__device__ __forceinline__ void upk(ull v, float& lo, float& hi){ asm("mov.b64 {%0, %1}, %2;" : "=f"(lo), "=f"(hi) : "l"(v)); }
__device__ __forceinline__ ull ffma2(ull a, ull b, ull c){ ull d; asm("fma.rn.f32x2 %0, %1, %2, %3;" : "=l"(d) : "l"(a), "l"(b), "l"(c)); return d; }
__device__ __forceinline__ ull fadd2(ull a, ull b){ ull d; asm("add.rn.f32x2 %0, %1, %2;" : "=l"(d) : "l"(a), "l"(b)); return d; }
__device__ __forceinline__ ull tanh2hw(ull v){ float lo, hi; upk(v, lo, hi); return pk(th_hw(lo), th_hw(hi)); }
__device__ __forceinline__ ull shfl16(ull v){
    unsigned lo = (unsigned)v, hi = (unsigned)(v >> 32);
    lo = __shfl_down_sync(0xffffffffu, lo, 16);
    hi = __shfl_down_sync(0xffffffffu, hi, 16);
    return ((ull)hi << 32) | lo;
}

// ---------------- SMEM layout (floats), 64-position tile ----------------
#define ATT_OFF 0                        // attrs[15][64]
#define PT_OFF  (ATT_OFF + 15*64)        // pt[3][64]
#define W1D_OFF (PT_OFF + 3*64)          // w1 dup [15][512]  (reused as g later)
#define B1_OFF  (W1D_OFF + 15*512)       // 256
#define B2_OFF  (B1_OFF + 256)           // 64
#define W3_OFF  (B2_OFF + 64)            // w3t[6][64]
#define B3_OFF  (W3_OFF + 6*64)          // 8
#define H_OFF   (B3_OFF + 8)             // h[256][64]
#define G_OFF   W1D_OFF                  // g[64][68] pos-major, padded (overlays w1d)
#define GPITCH  68
#define SMEM_FLOATS (H_OFF + 256*64)
#define SMEM_BYTES (SMEM_FLOATS * 4)     // 103712 B -> 2 CTAs/SM (RF-limited anyway)

__device__ __forceinline__ void emit_consts(int idx, float pet, float tmean, float prcp, const float p[6]){
    float tmin = p[0], tmax = p[1], ddf = p[2], f = p[3], sm0 = p[4], qm0 = p[5];
    float smax = fmaf(sm0, 1400.f, 100.f);
    float qmax = fmaf(qm0, 40.f, 10.f);
    float tmn   = tmin * (-3.f);
    float psnow = hv10(tmn - tmean) * prcp;
    float prain = prcp - psnow;
    float tmx3  = tmax * 3.f;
    float g     = hv10(tmean - tmx3);
    float m2    = (ddf * 5.f) * (tmean - tmx3);
    float fr2   = f * LFR;
    float C1t   = -5.f * smax;
    float C3    = pet + qmax - smax;
    float Bc    = pet * rcpf(smax);
    float C2    = lg2f(qmax) - fr2 * smax;
    float C4    = qmax - smax;
    g_pA[idx] = make_float4(psnow, prain, g, m2);
    g_pB[idx] = make_float4(C1t, C3, Bc, fr2);
    g_pC[idx] = make_float2(C2, C4);
}

// ============ scan (device function, run by CTAs 0..3) ============
__device__ void scan_body(int bid, int lane)
{
    const int b = bid * 32 + lane;
    const float4* pA = g_pA + b;
    const float4* pB = g_pB + b;
    const float2* pC = g_pC + b;

    // wait for chunk 0, then fill the 8-deep ring
    while (ld_acq(&g_flag[0]) < 64) __nanosleep(200);
    float4 bA[8], bC[8]; float bL[8];
    #pragma unroll
    for (int k = 0; k < 8; k++){
        bA[k] = pA[k*BB]; bC[k] = pB[k*BB]; bL[k] = pC[k*BB].x;
    }

    float s0 = 0.f, s1 = 0.f;
    #pragma unroll 1
    for (int c = 0; c < NCHUNK; c++){
        // one poll per 32 steps: chunk c+1 covers the <=8-plane prefetch lookahead
        const int wc = (c + 1 < NCHUNK) ? c + 1 : NCHUNK - 1;
        while (ld_acq(&g_flag[wc]) < 64) __nanosleep(200);

        #pragma unroll 1
        for (int t = c*32; t < c*32 + 32; t += 8){
            #pragma unroll
            for (int u = 0; u < 8; u++){
                float4 a = bA[u]; float4 cc = bC[u]; float lq = bL[u];
                int tn = t + u + 8; if (tn > TT-1) tn = TT-1;
                bA[u] = pA[tn*BB]; bC[u] = pB[tn*BB]; bL[u] = pC[tn*BB].x;

                // ---- snow bucket:  s0 += clip(psnow - melt) ----
                float s0pa = s0 + a.x;
                float s0lo = s0 - CLIPV, s0hi = s0 + CLIPV;
                float m0   = a.z * fminf(s0, a.w);
                float hs0  = fmaf(0.5f, th_hw(5.f * s0), 0.5f);
                float melt = hs0 * m0;

                // ---- soil bucket:  s1 += clip(prain + melt - loss) ----
                float s1lo = s1 - CLIPV, s1hi = s1 + CLIPV;
                float ays  = (a.y + s1);
                float tA    = th_hw(fmaf(5.f, s1, cc.x));
                float above = fmaf(0.5f, tA, 0.5f);
                float h1    = fmaf(0.5f, th_hw(5.f * s1), 0.5f);
                float E     = ex2f(fmaf(cc.w, s1, lq));
                float v     = fmaf(cc.z, s1, E);
                float g     = (cc.y + s1) - v;
                float w     = fmaf(above, g, v);
                float aym   = ays + melt;
                s1 = fmaxf(fminf(fmaf(-h1, w, aym), s1hi), s1lo);
                s0 = fmaxf(fminf(s0pa - melt, s0hi), s0lo);

                g_s1s[(t + u) * BB + b] = s1;
            }
        }
    }
}

// ============ fused kernel: mlp producer CTAs + scan consumer CTAs ============
__global__ __launch_bounds__(256, 2)
void fused_kernel(const float* __restrict__ in,
                  const float* __restrict__ w1, const float* __restrict__ b1,
                  const float* __restrict__ w2, const float* __restrict__ b2,
                  const float* __restrict__ w3, const float* __restrict__ b3)
{
    const int bid = blockIdx.x;
    const int tid = threadIdx.x;

    if (bid < 4){
        if (tid < 32) scan_body(bid, tid);
        return;
    }

    extern __shared__ float sm[];
    const int t   = (bid - 4) >> 1;
    const int hb  = (bid - 4) & 1;         // which 64-position half

    // ---- stage inputs ----
    {
        int r = tid >> 2, part = tid & 3;          // r: local row 0..63
        const float* base = in + ((size_t)(hb*64 + r) * TT + t) * 20;
        float4 q = *(const float4*)(base + part*4);
        if (part == 0){
            sm[PT_OFF + 0*64 + r] = q.x;           // pet
            sm[PT_OFF + 1*64 + r] = q.y;           // tmean
            sm[PT_OFF + 2*64 + r] = q.z;           // prcp
            float4 q4 = *(const float4*)(base + 16);
            sm[ATT_OFF + 11*64 + r] = q4.x; sm[ATT_OFF + 12*64 + r] = q4.y;
            sm[ATT_OFF + 13*64 + r] = q4.z; sm[ATT_OFF + 14*64 + r] = q4.w;
        } else if (part == 1){
            sm[ATT_OFF + 0*64 + r] = q.y; sm[ATT_OFF + 1*64 + r] = q.z; sm[ATT_OFF + 2*64 + r] = q.w;
        } else if (part == 2){
            sm[ATT_OFF + 3*64 + r] = q.x; sm[ATT_OFF + 4*64 + r] = q.y;
            sm[ATT_OFF + 5*64 + r] = q.z; sm[ATT_OFF + 6*64 + r] = q.w;
        } else {
            sm[ATT_OFF + 7*64 + r] = q.x; sm[ATT_OFF + 8*64 + r] = q.y;
            sm[ATT_OFF + 9*64 + r] = q.z; sm[ATT_OFF +10*64 + r] = q.w;
        }
    }
    // ---- stage duplicated w1 (dup at staging time) + small weights ----
    for (int idx = tid; idx < 15*256; idx += 256){
        int k = idx >> 8, i = idx & 255;
        float w = w1[idx];
        sm[W1D_OFF + k*512 + 2*i]     = w;
        sm[W1D_OFF + k*512 + 2*i + 1] = w;
    }
    sm[B1_OFF + tid] = b1[tid];
    if (tid < 64) sm[B2_OFF + tid] = b2[tid];
    for (int i = tid; i < 384; i += 256){ int m = i >> 6, j = i & 63; sm[W3_OFF + i] = w3[j*6 + m]; }
    if (tid < 8) sm[B3_OFF + tid] = (tid < 6) ? b3[tid] : 0.f;
    __syncthreads();

    // ---- stage A: layer 1 (15 -> 256) + tanh -> h[i][pos] ----
    // attrs hoisted to registers (loop-invariant across passes)
    // unroll 1 on passes: REQUIRED — unroll 2 spills under the 128-reg cap (R11)
    {
        const int bg = tid & 15;    // pos pairs {bg*2,bg*2+1} and {32+bg*2,32+bg*2+1}
        const int ig = tid >> 4;    // 16 hidden groups of 4

        ull aL[15], aH[15];
        #pragma unroll
        for (int k = 0; k < 15; k++){
            aL[k] = *(const ull*)(sm + ATT_OFF + k*64 + bg*2);
            aH[k] = *(const ull*)(sm + ATT_OFF + k*64 + 32 + bg*2);
        }

        #pragma unroll 1
        for (int pass = 0; pass < 4; pass++){
            const int i0 = pass*64 + ig*4;
            ull accL[4], accH[4];
            #pragma unroll
            for (int ii = 0; ii < 4; ii++){
                float bb = sm[B1_OFF + i0 + ii];
                accL[ii] = pk(bb, bb); accH[ii] = accL[ii];
            }
            #pragma unroll
            for (int k = 0; k < 15; k++){
                ulonglong2 w01 = *(const ulonglong2*)(sm + W1D_OFF + k*512 + i0*2);
                ulonglong2 w23 = *(const ulonglong2*)(sm + W1D_OFF + k*512 + i0*2 + 4);
                accL[0]=ffma2(aL[k],w01.x,accL[0]); accL[1]=ffma2(aL[k],w01.y,accL[1]);
                accL[2]=ffma2(aL[k],w23.x,accL[2]); accL[3]=ffma2(aL[k],w23.y,accL[3]);
                accH[0]=ffma2(aH[k],w01.x,accH[0]); accH[1]=ffma2(aH[k],w01.y,accH[1]);
                accH[2]=ffma2(aH[k],w23.x,accH[2]); accH[3]=ffma2(aH[k],w23.y,accH[3]);
            }
            #pragma unroll
            for (int ii = 0; ii < 4; ii++){
                *(ull*)(sm + H_OFF + (i0+ii)*64 + bg*2)      = tanh2hw(accL[ii]);
                *(ull*)(sm + H_OFF + (i0+ii)*64 + 32 + bg*2) = tanh2hw(accH[ii]);
            }
        }
    }
    __syncthreads();

    // ---- stage B: layer 2 (256 -> 64), (j,j+1) lanes, w2 from L2, induction ptrs ----
    {
        const int lane = tid & 31;
        const int wrp  = tid >> 5;       // warp = output group; j0 = wrp*8
        const int j0   = wrp * 8;
        const int pg   = lane & 15;      // 4 positions p0 = pg*4
        const int kg   = lane >> 4;      // split-K half
        const int ibase = kg * 128;

        ull acc[4][4];
        #pragma unroll
        for (int m = 0; m < 4; m++){
            ull bv = (kg == 0) ? *(const ull*)(sm + B2_OFF + j0 + 2*m) : 0ULL;
            acc[0][m] = bv; acc[1][m] = bv; acc[2][m] = bv; acc[3][m] = bv;
        }

        const char* rw  = (const char*)(w2 + ibase*64 + j0);   // row stride 256 B
        ulonglong2 wb[4][2];
        #pragma unroll
        for (int p = 0; p < 4; p++){
            wb[p][0] = __ldg((const ulonglong2*)(rw + p*256));
            wb[p][1] = __ldg((const ulonglong2*)(rw + p*256) + 1);
        }
        const char* rpf = rw + 4*256;

        #pragma unroll 4
        for (int ii = 0; ii < 124; ii++){
            const int slot = ii & 3;
            ull q0 = wb[slot][0].x, q1 = wb[slot][0].y;
            ull q2 = wb[slot][1].x, q3 = wb[slot][1].y;
            wb[slot][0] = __ldg((const ulonglong2*)rpf);
            wb[slot][1] = __ldg((const ulonglong2*)rpf + 1);
            rpf += 256;

            float4 hq = *(const float4*)(sm + H_OFF + (ibase+ii)*64 + pg*4);
            ull h0 = pk(hq.x,hq.x), h1 = pk(hq.y,hq.y), h2 = pk(hq.z,hq.z), h3 = pk(hq.w,hq.w);
            acc[0][0]=ffma2(h0,q0,acc[0][0]); acc[0][1]=ffma2(h0,q1,acc[0][1]); acc[0][2]=ffma2(h0,q2,acc[0][2]); acc[0][3]=ffma2(h0,q3,acc[0][3]);
            acc[1][0]=ffma2(h1,q0,acc[1][0]); acc[1][1]=ffma2(h1,q1,acc[1][1]); acc[1][2]=ffma2(h1,q2,acc[1][2]); acc[1][3]=ffma2(h1,q3,acc[1][3]);
            acc[2][0]=ffma2(h2,q0,acc[2][0]); acc[2][1]=ffma2(h2,q1,acc[2][1]); acc[2][2]=ffma2(h2,q2,acc[2][2]); acc[2][3]=ffma2(h2,q3,acc[2][3]);
            acc[3][0]=ffma2(h3,q0,acc[3][0]); acc[3][1]=ffma2(h3,q1,acc[3][1]); acc[3][2]=ffma2(h3,q2,acc[3][2]); acc[3][3]=ffma2(h3,q3,acc[3][3]);
        }
        #pragma unroll
        for (int ii = 124; ii < 128; ii++){
            const int slot = ii & 3;
            ull q0 = wb[slot][0].x, q1 = wb[slot][0].y;
            ull q2 = wb[slot][1].x, q3 = wb[slot][1].y;
            float4 hq = *(const float4*)(sm + H_OFF + (ibase+ii)*64 + pg*4);
            ull h0 = pk(hq.x,hq.x), h1 = pk(hq.y,hq.y), h2 = pk(hq.z,hq.z), h3 = pk(hq.w,hq.w);
            acc[0][0]=ffma2(h0,q0,acc[0][0]); acc[0][1]=ffma2(h0,q1,acc[0][1]); acc[0][2]=ffma2(h0,q2,acc[0][2]); acc[0][3]=ffma2(h0,q3,acc[0][3]);
            acc[1][0]=ffma2(h1,q0,acc[1][0]); acc[1][1]=ffma2(h1,q1,acc[1][1]); acc[1][2]=ffma2(h1,q2,acc[1][2]); acc[1][3]=ffma2(h1,q3,acc[1][3]);
            acc[2][0]=ffma2(h2,q0,acc[2][0]); acc[2][1]=ffma2(h2,q1,acc[2][1]); acc[2][2]=ffma2(h2,q2,acc[2][2]); acc[2][3]=ffma2(h2,q3,acc[2][3]);
            acc[3][0]=ffma2(h3,q0,acc[3][0]); acc[3][1]=ffma2(h3,q1,acc[3][1]); acc[3][2]=ffma2(h3,q2,acc[3][2]); acc[3][3]=ffma2(h3,q3,acc[3][3]);
        }

        // split-K reduction (lanes 16..31 -> 0..15)
        #pragma unroll
        for (int p = 0; p < 4; p++)
            #pragma unroll
            for (int m = 0; m < 4; m++)
                acc[p][m] = fadd2(acc[p][m], shfl16(acc[p][m]));

        __syncthreads();   // all h/w1d reads done; w1d region becomes g

        if (kg == 0){
            #pragma unroll
            for (int p = 0; p < 4; p++){
                const int row = pg*4 + p;
                ulonglong2 v01, v23;
                v01.x = tanh2hw(acc[p][0]); v01.y = tanh2hw(acc[p][1]);
                v23.x = tanh2hw(acc[p][2]); v23.y = tanh2hw(acc[p][3]);
                *(ulonglong2*)(sm + G_OFF + row*GPITCH + j0)     = v01;
                *(ulonglong2*)(sm + G_OFF + row*GPITCH + j0 + 4) = v23;
            }
        }
    }
    __syncthreads();

    // ---- stage C: layer 3 (64 -> 6) + sigmoid + emit ----
    if (tid < 64){
        const int b = tid;
        float s0c = sm[B3_OFF+0], s1c = sm[B3_OFF+1], s2c = sm[B3_OFF+2];
        float s3c = sm[B3_OFF+3], s4c = sm[B3_OFF+4], s5c = sm[B3_OFF+5];
        #pragma unroll
        for (int j = 0; j < 64; j += 4){
            float4 gq = *(const float4*)(sm + G_OFF + b*GPITCH + j);
            #pragma unroll
            for (int u = 0; u < 4; u++){
                float gv = (&gq.x)[u];
                s0c = fmaf(gv, sm[W3_OFF + 0*64 + j + u], s0c);
                s1c = fmaf(gv, sm[W3_OFF + 1*64 + j + u], s1c);
                s2c = fmaf(gv, sm[W3_OFF + 2*64 + j + u], s2c);
                s3c = fmaf(gv, sm[W3_OFF + 3*64 + j + u], s3c);
                s4c = fmaf(gv, sm[W3_OFF + 4*64 + j + u], s4c);
                s5c = fmaf(gv, sm[W3_OFF + 5*64 + j + u], s5c);
            }
        }
        float pr[6] = { sigm(s0c), sigm(s1c), sigm(s2c), sigm(s3c), sigm(s4c), sigm(s5c) };
        emit_consts(t*128 + hb*64 + b, sm[PT_OFF + b], sm[PT_OFF + 64 + b], sm[PT_OFF + 128 + b], pr);
    }

    // ---- publish chunk progress (release) ----
    __threadfence();
    __syncthreads();
    if (tid == 0) atomicAdd(&g_flag[t >> 5], 1);
}

// ============ kernel C: q = qsub+qsurf from stored s1 (4 t per thread) ============
// Also re-zeroes g_flag at the tail (block 0) for the next graph replay:
// qout runs strictly after all flag readers/writers of this replay, and the
// first-ever run sees the zero-initialized device globals. Same work every call.
__global__ __launch_bounds__(256)
void qout_kernel(float* __restrict__ out)
{
    const int i  = blockIdx.x * 256 + threadIdx.x;    // 0 .. NP/4-1
    const int b  = i & 127;
    const int t0 = (i >> 7) * 4;

    float qv[4];
    #pragma unroll
    for (int k = 0; k < 4; k++){
        const int idx = (t0 + k) * BB + b;
        float  s1 = g_s1s[idx];
        float4 c  = g_pB[idx];   // C1t, C3, Bc, fr2
        float2 e  = g_pC[idx];   // C2, C4
        float tA    = th_hw(fmaf(5.f, s1, c.x));
        float above = fmaf( 0.5f, tA, 0.5f);
        float below = fmaf(-0.5f, tA, 0.5f);
        float h1    = fmaf(0.5f, th_hw(5.f * s1), 0.5f);
        float E     = ex2f(fmaf(c.w, s1, e.x));
        qv[k] = h1 * (above * (e.y + s1) + below * E);
    }
    *(float4*)(out + (size_t)b * TT + t0) = make_float4(qv[0], qv[1], qv[2], qv[3]);

    if (blockIdx.x == 0 && threadIdx.x < NCHUNK) g_flag[threadIdx.x] = 0;
}

// ---------------- launch ----------------
extern "C" void kernel_launch(void* const* d_in, const int* in_sizes, int n_in,
                              void* d_out, int out_size)
{
    const float* in = (const float*)d_in[0];
    const float* w1 = (const float*)d_in[1];
    const float* b1 = (const float*)d_in[2];
    const float* w2 = (const float*)d_in[3];
    const float* b2 = (const float*)d_in[4];
    const float* w3 = (const float*)d_in[5];
    const float* b3 = (const float*)d_in[6];
    float* out = (float*)d_out;

    cudaFuncSetAttribute(fused_kernel, cudaFuncAttributeMaxDynamicSharedMemorySize, SMEM_BYTES);
    fused_kernel<<<TT*2 + 4, 256, SMEM_BYTES>>>(in, w1, b1, w2, b2, w3, b3);
    qout_kernel<<<NP/4/256, 256>>>(out);
}